// round 2
// baseline (speedup 1.0000x reference)
#include <cuda_runtime.h>

#define BB 8
#define NN 2048
#define DD 128

// 1/(2*sqrt(128)): reference scales A by 1/sqrt(D) then entmax divides by 2
#define ENTMAX_SCALE 0.04419417382415922f

// Scratch for projected Q and K (8 MB each) — static device arrays (no alloc).
__device__ float g_Q[BB * NN * DD];
__device__ float g_K[BB * NN * DD];

// ---------------------------------------------------------------------------
// Kernel 1: row-major projection  out[r][d] = sum_k x[r][k] * W[d][k] + b[d]
// 128 threads (thread = output col d), 64 rows per CTA, W staged in smem.
// ---------------------------------------------------------------------------
#define P_PITCH 132           // floats; 132%4==0 (float4 aligned), conflict-free phases
#define P_ROWS  64
#define P_SMEM  ((128 * P_PITCH + 4 * 128) * 4)

__global__ void proj_kernel(const float* __restrict__ x,
                            const float* __restrict__ W,
                            const float* __restrict__ bias,
                            int which)
{
    extern __shared__ float sm[];
    float* Wsh = sm;                    // [128][P_PITCH]
    float* xs  = sm + 128 * P_PITCH;    // [4][128]
    float* out = which ? g_K : g_Q;

    const int tid = threadIdx.x;        // 0..127

    // Stage W: row j of W -> Wsh[j*P_PITCH + k]; writes conflict-free (stride 1)
    #pragma unroll 16
    for (int j = 0; j < 128; j++)
        Wsh[j * P_PITCH + tid] = W[j * 128 + tid];
    const float bb = bias[tid];
    __syncthreads();

    const int base = blockIdx.x * P_ROWS;

    for (int q = 0; q < P_ROWS / 4; q++) {
        #pragma unroll
        for (int r = 0; r < 4; r++)
            xs[r * 128 + tid] = x[(base + q * 4 + r) * 128 + tid];
        __syncthreads();

        float a0 = bb, a1 = bb, a2 = bb, a3 = bb;
        #pragma unroll 8
        for (int k4 = 0; k4 < 32; k4++) {
            float4 w  = *(const float4*)&Wsh[tid * P_PITCH + 4 * k4];
            float4 v0 = *(const float4*)&xs[0 * 128 + 4 * k4];
            float4 v1 = *(const float4*)&xs[1 * 128 + 4 * k4];
            float4 v2 = *(const float4*)&xs[2 * 128 + 4 * k4];
            float4 v3 = *(const float4*)&xs[3 * 128 + 4 * k4];
            a0 = fmaf(w.x, v0.x, a0); a0 = fmaf(w.y, v0.y, a0);
            a0 = fmaf(w.z, v0.z, a0); a0 = fmaf(w.w, v0.w, a0);
            a1 = fmaf(w.x, v1.x, a1); a1 = fmaf(w.y, v1.y, a1);
            a1 = fmaf(w.z, v1.z, a1); a1 = fmaf(w.w, v1.w, a1);
            a2 = fmaf(w.x, v2.x, a2); a2 = fmaf(w.y, v2.y, a2);
            a2 = fmaf(w.z, v2.z, a2); a2 = fmaf(w.w, v2.w, a2);
            a3 = fmaf(w.x, v3.x, a3); a3 = fmaf(w.y, v3.y, a3);
            a3 = fmaf(w.z, v3.z, a3); a3 = fmaf(w.w, v3.w, a3);
        }
        out[(base + q * 4 + 0) * 128 + tid] = a0;
        out[(base + q * 4 + 1) * 128 + tid] = a1;
        out[(base + q * 4 + 2) * 128 + tid] = a2;
        out[(base + q * 4 + 3) * 128 + tid] = a3;
        __syncthreads();
    }
}

// ---------------------------------------------------------------------------
// Kernel 2: fused A = Q K^T * scale  +  1.5-entmax per row (Newton, no sort).
// CTA = 256 threads = 8 warps. Warp w owns query row (tile*8 + w); its 2048
// attention logits live in registers: 64 floats per lane
//   acc[t*4+i]  <->  column  t*128 + tx + 32*i      (t = 0..15, i = 0..3)
// K tile staged transposed Ksh[k][m], pitch 129 (conflict-free both ways).
// ---------------------------------------------------------------------------
#define KP     129
#define A_SMEM ((8 * 128 + 128 * KP) * 4)

__global__ void attn_entmax_kernel(float* __restrict__ out)
{
    extern __shared__ float sm[];
    float* Qs  = sm;              // [8][128]
    float* Ksh = sm + 8 * 128;    // [128][KP]

    const int tid = threadIdx.x;
    const int tx  = tid & 31;
    const int wy  = tid >> 5;          // warp id = local query row

    const int b    = blockIdx.x >> 8;  // 256 row-tiles per batch
    const int tile = blockIdx.x & 255;
    const int row0 = tile * 8;

    const float* __restrict__ Qb = g_Q + b * (NN * DD);
    const float* __restrict__ Kb = g_K + b * (NN * DD);

    // Load Q tile: 1024 floats
    #pragma unroll
    for (int j = 0; j < 4; j++) {
        int idx = j * 256 + tid;                    // idx = r*128 + k
        Qs[idx] = Qb[(row0 + (idx >> 7)) * 128 + (idx & 127)];
    }

    float acc[64];

    #pragma unroll
    for (int t = 0; t < 16; t++) {
        __syncthreads();   // protects Qs (t=0) and Ksh reuse (t>0)
        // Stage K tile transposed: global read coalesced (lanes consecutive k),
        // smem writes conflict-free (delta addr = KP = 129 -> bank +1)
        #pragma unroll 8
        for (int j = 0; j < 64; j++) {
            int idx = j * 256 + tid;
            int m = idx >> 7, k = idx & 127;
            Ksh[k * KP + m] = Kb[(t * 128 + m) * 128 + k];
        }
        __syncthreads();

        float a0 = 0.f, a1 = 0.f, a2 = 0.f, a3 = 0.f;
        const float* qrow = Qs + wy * 128;
        #pragma unroll 4
        for (int k = 0; k < 128; k++) {
            float q = qrow[k];                       // warp broadcast
            const float* kr = Ksh + k * KP + tx;     // lanes stride-1: no conflict
            a0 = fmaf(q, kr[0],  a0);
            a1 = fmaf(q, kr[32], a1);
            a2 = fmaf(q, kr[64], a2);
            a3 = fmaf(q, kr[96], a3);
        }
        acc[t * 4 + 0] = a0; acc[t * 4 + 1] = a1;
        acc[t * 4 + 2] = a2; acc[t * 4 + 3] = a3;
    }

    // ---- entmax15 over the 2048 logits of this warp's row ----
    // z = acc * scale, shifted so max(z) = 0
    float zmax = -1e30f;
    #pragma unroll
    for (int i = 0; i < 64; i++) {
        acc[i] *= ENTMAX_SCALE;
        zmax = fmaxf(zmax, acc[i]);
    }
    #pragma unroll
    for (int o = 16; o; o >>= 1)
        zmax = fmaxf(zmax, __shfl_xor_sync(0xffffffffu, zmax, o));
    #pragma unroll
    for (int i = 0; i < 64; i++) acc[i] -= zmax;

    // tau = root of f(tau) = sum((z - tau)_+^2) - 1  (convex, decreasing).
    // Monotone Newton from tau = -1 (f(-1) >= 0, never overshoots).
    float tau = -1.0f;
    for (int it = 0; it < 50; it++) {
        float s1 = 0.f, s2 = 0.f;
        #pragma unroll
        for (int i = 0; i < 64; i++) {
            float d = fmaxf(acc[i] - tau, 0.f);
            s1 += d;
            s2 = fmaf(d, d, s2);
        }
        #pragma unroll
        for (int o = 16; o; o >>= 1) {
            s1 += __shfl_xor_sync(0xffffffffu, s1, o);
            s2 += __shfl_xor_sync(0xffffffffu, s2, o);
        }
        float f = s2 - 1.0f;
        if (f < 1e-5f) break;          // tau error <= f/(2*s1): far below 1e-3
        tau += f / (2.0f * s1);        // s1 > 0 whenever f > 0
    }

    // p = (z - tau)_+^2 ; coalesced stores (lanes = consecutive columns)
    float* __restrict__ orow = out + ((long)(b * NN + row0 + wy)) * NN;
    #pragma unroll
    for (int t = 0; t < 16; t++) {
        #pragma unroll
        for (int i = 0; i < 4; i++) {
            float d = fmaxf(acc[t * 4 + i] - tau, 0.f);
            orow[t * 128 + tx + 32 * i] = d * d;
        }
    }
}

// ---------------------------------------------------------------------------
extern "C" void kernel_launch(void* const* d_in, const int* in_sizes, int n_in,
                              void* d_out, int out_size)
{
    const float* x_c = (const float*)d_in[0];
    const float* x_n = (const float*)d_in[1];
    const float* Wq  = (const float*)d_in[2];
    const float* bq  = (const float*)d_in[3];
    const float* Wk  = (const float*)d_in[4];
    const float* bk  = (const float*)d_in[5];

    // Idempotent, called every launch (no static guards). Not a stream op ->
    // legal under graph capture.
    cudaFuncSetAttribute(proj_kernel,
                         cudaFuncAttributeMaxDynamicSharedMemorySize, P_SMEM);
    cudaFuncSetAttribute(attn_entmax_kernel,
                         cudaFuncAttributeMaxDynamicSharedMemorySize, A_SMEM);

    proj_kernel<<<BB * NN / P_ROWS, 128, P_SMEM>>>(x_c, Wq, bq, 0);
    proj_kernel<<<BB * NN / P_ROWS, 128, P_SMEM>>>(x_n, Wk, bk, 1);
    attn_entmax_kernel<<<BB * (NN / 8), 256, A_SMEM>>>((float*)d_out);
}

// round 5
// speedup vs baseline: 3.5407x; 3.5407x over previous
#include <cuda_runtime.h>
#include <cuda_bf16.h>

#define BB 8
#define NN 2048
#define DD 128

// 1/(2*sqrt(128)): reference scales A by 1/sqrt(D) then entmax divides by 2.
// Folded into Q at projection time.
#define ENTMAX_SCALE 0.04419417382415922f

// Static scratch (no alloc allowed): split-bf16 Q/K and fp32 logits.
__device__ __nv_bfloat16 g_Qh[BB * NN * DD];
__device__ __nv_bfloat16 g_Ql[BB * NN * DD];
__device__ __nv_bfloat16 g_Kh[BB * NN * DD];
__device__ __nv_bfloat16 g_Kl[BB * NN * DD];
__device__ float        g_A[(long)BB * NN * NN];   // 134 MB raw logits

__device__ __forceinline__ unsigned smem_u32(const void* p) {
    unsigned a;
    asm("{ .reg .u64 t; cvta.to.shared.u64 t, %1; cvt.u32.u64 %0, t; }"
        : "=r"(a) : "l"(p));
    return a;
}

#define LDSM_X4(r0, r1, r2, r3, addr) \
    asm volatile("ldmatrix.sync.aligned.m8n8.x4.shared.b16 {%0,%1,%2,%3}, [%4];" \
                 : "=r"(r0), "=r"(r1), "=r"(r2), "=r"(r3) : "r"(addr))

#define MMA_BF16(c, a0, a1, a2, a3, b0, b1) \
    asm volatile("mma.sync.aligned.m16n8k16.row.col.f32.bf16.bf16.f32 " \
                 "{%0,%1,%2,%3}, {%4,%5,%6,%7}, {%8,%9}, {%0,%1,%2,%3};" \
                 : "+f"((c)[0]), "+f"((c)[1]), "+f"((c)[2]), "+f"((c)[3]) \
                 : "r"(a0), "r"(a1), "r"(a2), "r"(a3), "r"(b0), "r"(b1))

// ---------------------------------------------------------------------------
// Kernel 1: projection  out[r][d] = sum_k x[r][k]*W[d][k] + b[d], split bf16.
// blockIdx < 256 -> Q path (scaled by ENTMAX_SCALE), >= 256 -> K path.
// ---------------------------------------------------------------------------
#define P_PITCH 132
#define P_ROWS  64
#define P_SMEM  ((128 * P_PITCH + 4 * 128) * 4)

__global__ void proj_kernel(const float* __restrict__ x_c,
                            const float* __restrict__ x_n,
                            const float* __restrict__ Wq,
                            const float* __restrict__ bq,
                            const float* __restrict__ Wk,
                            const float* __restrict__ bk)
{
    extern __shared__ float sm[];
    float* Wsh = sm;
    float* xs  = sm + 128 * P_PITCH;

    const int which = (blockIdx.x >= 256);
    const float* x    = which ? x_n : x_c;
    const float* W    = which ? Wk  : Wq;
    const float* bias = which ? bk  : bq;
    __nv_bfloat16* oh = which ? g_Kh : g_Qh;
    __nv_bfloat16* ol = which ? g_Kl : g_Ql;
    const float scale = which ? 1.0f : ENTMAX_SCALE;

    const int tid = threadIdx.x;

    #pragma unroll 16
    for (int j = 0; j < 128; j++)
        Wsh[j * P_PITCH + tid] = W[j * 128 + tid];
    const float bb = bias[tid];
    __syncthreads();

    const int base = (blockIdx.x & 255) * P_ROWS;

    for (int q = 0; q < P_ROWS / 4; q++) {
        #pragma unroll
        for (int r = 0; r < 4; r++)
            xs[r * 128 + tid] = x[(base + q * 4 + r) * 128 + tid];
        __syncthreads();

        float a0 = bb, a1 = bb, a2 = bb, a3 = bb;
        #pragma unroll 8
        for (int k4 = 0; k4 < 32; k4++) {
            float4 w  = *(const float4*)&Wsh[tid * P_PITCH + 4 * k4];
            float4 v0 = *(const float4*)&xs[0 * 128 + 4 * k4];
            float4 v1 = *(const float4*)&xs[1 * 128 + 4 * k4];
            float4 v2 = *(const float4*)&xs[2 * 128 + 4 * k4];
            float4 v3 = *(const float4*)&xs[3 * 128 + 4 * k4];
            a0 = fmaf(w.x, v0.x, a0); a0 = fmaf(w.y, v0.y, a0);
            a0 = fmaf(w.z, v0.z, a0); a0 = fmaf(w.w, v0.w, a0);
            a1 = fmaf(w.x, v1.x, a1); a1 = fmaf(w.y, v1.y, a1);
            a1 = fmaf(w.z, v1.z, a1); a1 = fmaf(w.w, v1.w, a1);
            a2 = fmaf(w.x, v2.x, a2); a2 = fmaf(w.y, v2.y, a2);
            a2 = fmaf(w.z, v2.z, a2); a2 = fmaf(w.w, v2.w, a2);
            a3 = fmaf(w.x, v3.x, a3); a3 = fmaf(w.y, v3.y, a3);
            a3 = fmaf(w.z, v3.z, a3); a3 = fmaf(w.w, v3.w, a3);
        }
        #pragma unroll
        for (int r = 0; r < 4; r++) {
            float v = ((r == 0) ? a0 : (r == 1) ? a1 : (r == 2) ? a2 : a3) * scale;
            __nv_bfloat16 h = __float2bfloat16(v);
            float lo = v - __bfloat162float(h);
            long idx = (long)(base + q * 4 + r) * 128 + tid;
            oh[idx] = h;
            ol[idx] = __float2bfloat16(lo);
        }
        __syncthreads();
    }
}

// ---------------------------------------------------------------------------
// Kernel 2: split-bf16 HMMA GEMM  g_A[b][m][n] = Qs[b,m] . K[b,n]
// CTA: 256 threads (8 warps, 4x2), tile M=128 x N=128, K=128 resident.
// smem tiles at half-pitch 136 (272 B): ldmatrix phase-conflict-free.
// ---------------------------------------------------------------------------
#define PITCH_H 136
#define PITCH_B 272
#define T_BYTES (128 * PITCH_B)      // 34816 per tile
#define SM_QH   0
#define SM_QL   (T_BYTES)
#define SM_KH   (2 * T_BYTES)
#define SM_KL   (3 * T_BYTES)
#define G_SMEM  (4 * T_BYTES)        // 139264

__device__ __forceinline__ void stage_tile(char* smem, int off,
                                           const __nv_bfloat16* src, int tid)
{
    const uint4* s = (const uint4*)src;          // 8 halves per uint4
    #pragma unroll
    for (int i = 0; i < 8; i++) {
        int idx = i * 256 + tid;                 // idx = row*16 + c8
        int row = idx >> 4, c8 = idx & 15;
        *(uint4*)(smem + off + row * PITCH_B + c8 * 16) = s[idx];
    }
}

__global__ void __launch_bounds__(256, 1)
qk_mma_kernel()
{
    extern __shared__ char smem[];
    const unsigned sb = smem_u32(smem);
    const int tid  = threadIdx.x;
    const int wid  = tid >> 5;
    const int lane = tid & 31;
    const int wm   = (wid & 3) * 32;             // warp M offset (rows)
    const int wn   = (wid >> 2) * 64;            // warp N offset (cols)

    const int b   = blockIdx.x >> 8;             // 256 tiles per batch
    const int rem = blockIdx.x & 255;
    const int m0  = (rem >> 4) << 7;
    const int n0  = (rem & 15) << 7;

    const long qb = (long)(b * NN + m0) * DD;
    const long kb = (long)(b * NN + n0) * DD;
    stage_tile(smem, SM_QH, g_Qh + qb, tid);
    stage_tile(smem, SM_QL, g_Ql + qb, tid);
    stage_tile(smem, SM_KH, g_Kh + kb, tid);
    stage_tile(smem, SM_KL, g_Kl + kb, tid);
    __syncthreads();

    float acc[2][8][4];
    #pragma unroll
    for (int mt = 0; mt < 2; mt++)
        #pragma unroll
        for (int nt = 0; nt < 8; nt++)
            #pragma unroll
            for (int j = 0; j < 4; j++) acc[mt][nt][j] = 0.f;

    // ldmatrix lane addressing (same pattern for A .x4 and B .x4):
    // lanes 0-15: rows base+(l&15), col +0 ; lanes 16-31: same rows, col +8
    const int lrow = lane & 15;
    const int lcol = (lane >> 4) * 8;

    #pragma unroll
    for (int pass = 0; pass < 3; pass++) {
        const int qoff = (pass == 2) ? SM_QL : SM_QH;
        const int koff = (pass == 1) ? SM_KL : SM_KH;

        unsigned a[2][8][4];
        #pragma unroll
        for (int mt = 0; mt < 2; mt++)
            #pragma unroll
            for (int kt = 0; kt < 8; kt++) {
                unsigned addr = sb + qoff + (wm + mt * 16 + lrow) * PITCH_B
                              + (kt * 16 + lcol) * 2;
                LDSM_X4(a[mt][kt][0], a[mt][kt][1], a[mt][kt][2], a[mt][kt][3], addr);
            }

        #pragma unroll
        for (int ntp = 0; ntp < 4; ntp++) {      // pair of n-tiles (16 keys)
            #pragma unroll
            for (int kt = 0; kt < 8; kt++) {
                unsigned b0, b1, b2, b3;
                unsigned addr = sb + koff + (wn + ntp * 16 + lrow) * PITCH_B
                              + (kt * 16 + lcol) * 2;
                LDSM_X4(b0, b1, b2, b3, addr);
                #pragma unroll
                for (int mt = 0; mt < 2; mt++) {
                    MMA_BF16(acc[mt][2 * ntp + 0], a[mt][kt][0], a[mt][kt][1],
                             a[mt][kt][2], a[mt][kt][3], b0, b2);
                    MMA_BF16(acc[mt][2 * ntp + 1], a[mt][kt][0], a[mt][kt][1],
                             a[mt][kt][2], a[mt][kt][3], b1, b3);
                }
            }
        }
    }

    // Epilogue: c-fragment direct stores (float2; 4 lanes cover 32B sectors)
    const int crow = lane >> 2;
    const int ccol = (lane & 3) * 2;
    float* base = g_A + (long)(b * NN + m0 + wm) * NN + n0 + wn;
    #pragma unroll
    for (int mt = 0; mt < 2; mt++)
        #pragma unroll
        for (int nt = 0; nt < 8; nt++) {
            float* p0 = base + (long)(mt * 16 + crow) * NN + nt * 8 + ccol;
            *(float2*)p0              = make_float2(acc[mt][nt][0], acc[mt][nt][1]);
            *(float2*)(p0 + 8LL * NN) = make_float2(acc[mt][nt][2], acc[mt][nt][3]);
        }
}

// ---------------------------------------------------------------------------
// Kernel 3: 1.5-entmax per row (sort-free monotone Newton), streaming g_A.
// Row per warp, 64 logits per lane via float4 (coalesced).
// ---------------------------------------------------------------------------
__global__ void __launch_bounds__(256)
entmax_kernel(float* __restrict__ out)
{
    const int tid = threadIdx.x;
    const int tx  = tid & 31;
    const int wy  = tid >> 5;
    const long row = (long)(blockIdx.x >> 8) * NN + (blockIdx.x & 255) * 8 + wy;

    const float4* src = (const float4*)(g_A + row * NN);
    float acc[64];
    float zmax = -1e30f;
    #pragma unroll
    for (int t = 0; t < 16; t++) {
        float4 v = src[t * 32 + tx];
        acc[t*4+0] = v.x; acc[t*4+1] = v.y; acc[t*4+2] = v.z; acc[t*4+3] = v.w;
        zmax = fmaxf(zmax, fmaxf(fmaxf(v.x, v.y), fmaxf(v.z, v.w)));
    }
    #pragma unroll
    for (int o = 16; o; o >>= 1)
        zmax = fmaxf(zmax, __shfl_xor_sync(0xffffffffu, zmax, o));
    #pragma unroll
    for (int i = 0; i < 64; i++) acc[i] -= zmax;

    // tau = root of f(tau) = sum((z-tau)_+^2) - 1 (convex, decreasing);
    // monotone Newton from tau=-1 never overshoots.
    float tau = -1.0f;
    for (int it = 0; it < 50; it++) {
        float s1 = 0.f, s2 = 0.f;
        #pragma unroll
        for (int i = 0; i < 64; i++) {
            float d = fmaxf(acc[i] - tau, 0.f);
            s1 += d;
            s2 = fmaf(d, d, s2);
        }
        #pragma unroll
        for (int o = 16; o; o >>= 1) {
            s1 += __shfl_xor_sync(0xffffffffu, s1, o);
            s2 += __shfl_xor_sync(0xffffffffu, s2, o);
        }
        float f = s2 - 1.0f;
        if (f < 1e-5f) break;
        tau += f / (2.0f * s1);
    }

    float4* dst = (float4*)(out + row * NN);
    #pragma unroll
    for (int t = 0; t < 16; t++) {
        float d0 = fmaxf(acc[t*4+0] - tau, 0.f);
        float d1 = fmaxf(acc[t*4+1] - tau, 0.f);
        float d2 = fmaxf(acc[t*4+2] - tau, 0.f);
        float d3 = fmaxf(acc[t*4+3] - tau, 0.f);
        dst[t * 32 + tx] = make_float4(d0*d0, d1*d1, d2*d2, d3*d3);
    }
}

// ---------------------------------------------------------------------------
extern "C" void kernel_launch(void* const* d_in, const int* in_sizes, int n_in,
                              void* d_out, int out_size)
{
    const float* x_c = (const float*)d_in[0];
    const float* x_n = (const float*)d_in[1];
    const float* Wq  = (const float*)d_in[2];
    const float* bq  = (const float*)d_in[3];
    const float* Wk  = (const float*)d_in[4];
    const float* bk  = (const float*)d_in[5];

    cudaFuncSetAttribute(proj_kernel,
                         cudaFuncAttributeMaxDynamicSharedMemorySize, P_SMEM);
    cudaFuncSetAttribute(qk_mma_kernel,
                         cudaFuncAttributeMaxDynamicSharedMemorySize, G_SMEM);

    proj_kernel<<<512, 128, P_SMEM>>>(x_c, x_n, Wq, bq, Wk, bk);
    qk_mma_kernel<<<BB * 256, 256, G_SMEM>>>();
    entmax_kernel<<<BB * (NN / 8), 256>>>((float*)d_out);
}